// round 15
// baseline (speedup 1.0000x reference)
#include <cuda_runtime.h>
#include <math.h>

#define D 8192
#define M_TIME 16
#define RMS_EPS 1e-6f
#define DEN_EPS 1e-9f
#define KTOP 1024  // D/8

// Scratch (no allocations allowed)
__device__ __align__(16) float g_x[D];
__device__ __align__(16) float g_r[D];
__device__ __align__(16) float g_k[D];
__device__ __align__(16) float g_v[D];
__device__ __align__(16) float g_y[D];
__device__ __align__(16) float g_h[D];
__device__ unsigned g_hist12[4096];   // 12-bit |h| histogram, built by mv_o

__device__ __forceinline__ float warp_sum(float v) {
    #pragma unroll
    for (int o = 16; o > 0; o >>= 1) v += __shfl_down_sync(0xffffffffu, v, o);
    return v;
}

// Inclusive suffix sum across 1024 threads (value per thread). All 1024
// threads must call. Caller must __syncthreads() before wsum is reused.
__device__ __forceinline__ unsigned suffix_incl_1024(unsigned val,
                                                     unsigned* wsum,
                                                     int lane, int wid) {
    unsigned v = val;
    #pragma unroll
    for (int o = 1; o < 32; o <<= 1) {
        unsigned u = __shfl_down_sync(0xffffffffu, v, o);
        if (lane + o < 32) v += u;
    }
    if (lane == 0) wsum[wid] = v;     // warp total
    __syncthreads();
    unsigned hi = 0;
    #pragma unroll
    for (int w = 0; w < 32; w++)
        if (w > wid) hi += wsum[w];
    return v + hi;                    // sum over all threads with index >= t
}

// ---------------------------------------------------------------------------
// K1: x = rmsnorm(x_in + pred) * norm_w      (1 block, 1024 threads)
// ---------------------------------------------------------------------------
__global__ void k_rms(const float* __restrict__ x_in,
                      const float* __restrict__ pred,
                      const float* __restrict__ norm_w) {
    __shared__ float sh[32];
    __shared__ float s_inv;
    const int t = threadIdx.x;  // 1024
    float vals[8];
    float acc = 0.f;
    #pragma unroll
    for (int j = 0; j < 8; j++) {
        int i = t + j * 1024;
        float a = x_in[i] + pred[i];
        vals[j] = a;
        acc = fmaf(a, a, acc);
    }
    acc = warp_sum(acc);
    const int lane = t & 31, wid = t >> 5;
    if (lane == 0) sh[wid] = acc;
    __syncthreads();
    if (wid == 0) {
        float v = sh[lane];
        v = warp_sum(v);
        if (lane == 0) s_inv = rsqrtf(v * (1.0f / D) + RMS_EPS);
    }
    __syncthreads();
    const float inv = s_inv;
    #pragma unroll
    for (int j = 0; j < 8; j++) {
        int i = t + j * 1024;
        g_x[i] = vals[j] * inv * norm_w[i];
    }
}

// ---------------------------------------------------------------------------
// K2: r = sigmoid(Wr@x), k = Wk@x, v = Wv@x   (3*8192 blocks, 256 threads)
//     PDL: prefetch the block's weight slice BEFORE the dependency sync.
// ---------------------------------------------------------------------------
__global__ void __launch_bounds__(256) k_mv3(const float* __restrict__ Wr,
                                             const float* __restrict__ Wk,
                                             const float* __restrict__ Wv) {
    const int bid = blockIdx.x;
    const int mat = bid >> 13;           // 0..2
    const int row = bid & (D - 1);
    const float* W = (mat == 0 ? Wr : (mat == 1 ? Wk : Wv)) + (size_t)row * D;
    const float4* __restrict__ W4 = (const float4*)W;
    const float4* __restrict__ X4 = (const float4*)g_x;
    const int t = threadIdx.x;

    float4 w[8];
    #pragma unroll
    for (int j = 0; j < 8; j++) w[j] = W4[t + j * 256];

    cudaGridDependencySynchronize();

    float acc = 0.f;
    #pragma unroll
    for (int j = 0; j < 8; j++) {
        float4 x = X4[t + j * 256];
        acc = fmaf(w[j].x, x.x, acc);
        acc = fmaf(w[j].y, x.y, acc);
        acc = fmaf(w[j].z, x.z, acc);
        acc = fmaf(w[j].w, x.w, acc);
    }
    __shared__ float sh[8];
    acc = warp_sum(acc);
    const int lane = t & 31, wid = t >> 5;
    if (lane == 0) sh[wid] = acc;
    __syncthreads();
    if (t == 0) {
        float s = sh[0];
        #pragma unroll
        for (int i = 1; i < 8; i++) s += sh[i];
        if (mat == 0)      g_r[row] = 1.0f / (1.0f + __expf(-s));
        else if (mat == 1) g_k[row] = s;
        else               g_v[row] = s;
    }
}

// ---------------------------------------------------------------------------
// K3: decay/RoPE/gating -> y                 (32 blocks, 256 threads)
//     Pre-sync region also zeroes g_hist12 for this invocation (independent
//     of mv3; strictly ordered before mv_o's atomics by the PDL chain).
// ---------------------------------------------------------------------------
__global__ void k_gate(const float* __restrict__ state_num,
                       const float* __restrict__ state_den,
                       const float* __restrict__ decay_param,
                       const float* __restrict__ W_time,
                       const float* __restrict__ step_pos,
                       const int*   __restrict__ dt) {
    const int i = blockIdx.x * blockDim.x + threadIdx.x;

    if (i < 4096) g_hist12[i] = 0;     // reset histogram each call

    // Independent of mv3 outputs — issue before the dependency sync.
    float sn_in = state_num[i];
    float sd_in = state_den[i];
    float dp    = decay_param[i];
    int   n     = dt[0];
    float sp    = step_pos[0];

    float s = 1.0f / (1.0f + expf(-dp));
    float lam = s * s;
    float mul = 1.0f;
    for (int j = 0; j < n; j++) mul *= lam;

    cudaGridDependencySynchronize();

    float v = g_v[i];
    if (i < 2 * M_TIME) {
        int p = i >> 1;
        float th = sp * W_time[p];
        float c, sn_;
        sincosf(th, &sn_, &c);
        float v0 = g_v[2 * p];
        float v1 = g_v[2 * p + 1];
        v = (i & 1) ? (v0 * sn_ + v1 * c) : (v0 * c - v1 * sn_);
    }

    float w = expf(g_k[i]);
    float num = sn_in * mul * lam + w * v;
    float den = sd_in * mul * lam + w;
    g_y[i] = g_r[i] * (num / (den + DEN_EPS));
}

// ---------------------------------------------------------------------------
// K4: h = x + Wo@y                           (8192 blocks, 256 threads)
//     Epilogue also contributes one atomic to the 12-bit |h| histogram,
//     giving kwta its first radix pass for free.
// ---------------------------------------------------------------------------
__global__ void __launch_bounds__(256) k_mv_o(const float* __restrict__ Wo) {
    const int row = blockIdx.x;
    const float4* __restrict__ W4 = (const float4*)(Wo + (size_t)row * D);
    const float4* __restrict__ Y4 = (const float4*)g_y;
    const int t = threadIdx.x;

    float4 w[8];
    #pragma unroll
    for (int j = 0; j < 8; j++) w[j] = W4[t + j * 256];

    cudaGridDependencySynchronize();

    float acc = 0.f;
    #pragma unroll
    for (int j = 0; j < 8; j++) {
        float4 y = Y4[t + j * 256];
        acc = fmaf(w[j].x, y.x, acc);
        acc = fmaf(w[j].y, y.y, acc);
        acc = fmaf(w[j].z, y.z, acc);
        acc = fmaf(w[j].w, y.w, acc);
    }
    __shared__ float sh[8];
    acc = warp_sum(acc);
    const int lane = t & 31, wid = t >> 5;
    if (lane == 0) sh[wid] = acc;
    __syncthreads();
    if (t == 0) {
        float s = sh[0];
        #pragma unroll
        for (int i = 1; i < 8; i++) s += sh[i];
        float hval = g_x[row] + s;
        g_h[row] = hval;
        atomicAdd(&g_hist12[__float_as_uint(fabsf(hval)) >> 20], 1u);
    }
}

// ---------------------------------------------------------------------------
// K5: kWTA — exact k-th largest |h|. Pass 1 (12 bits) comes prebuilt from
//     mv_o's histogram; passes 2-3 (10 bits each) refine over candidates.
//     (1 block, 1024 threads)
// ---------------------------------------------------------------------------
__global__ void k_kwta(float* __restrict__ out) {
    cudaGridDependencySynchronize();
    __shared__ unsigned wsum[32];
    __shared__ unsigned hist[1024];
    __shared__ unsigned s_pref, s_k;
    const int t = threadIdx.x;  // 1024
    const int lane = t & 31, wid = t >> 5;

    unsigned bits[8];
    #pragma unroll
    for (int j = 0; j < 8; j++)
        bits[j] = __float_as_uint(fabsf(g_h[t + j * 1024]));

    // ---- pass 1: 12-bit bucket from the prebuilt global histogram
    unsigned h4[4], localsum = 0;
    #pragma unroll
    for (int b = 0; b < 4; b++) { h4[b] = g_hist12[t * 4 + b]; localsum += h4[b]; }
    unsigned T = suffix_incl_1024(localsum, wsum, lane, wid);
    {
        unsigned run = T - localsum;         // count of bins >= 4(t+1)
        #pragma unroll
        for (int b = 3; b >= 0; b--) {       // bins descending: 4t+3 .. 4t
            unsigned S = run + h4[b];
            if (S >= KTOP && run < KTOP)     // S - h == run
                { s_pref = (unsigned)(t * 4 + b); s_k = KTOP - run; }
            run = S;
        }
    }
    __syncthreads();
    unsigned pref = s_pref;                  // 12-bit prefix
    unsigned kk = s_k;
    __syncthreads();

    // ---- pass 2: middle 10 bits among (bits>>20)==pref
    hist[t] = 0;
    __syncthreads();
    #pragma unroll
    for (int j = 0; j < 8; j++)
        if ((bits[j] >> 20) == pref)
            atomicAdd(&hist[(bits[j] >> 10) & 0x3FFu], 1u);
    __syncthreads();
    unsigned hv = hist[t];
    unsigned T2 = suffix_incl_1024(hv, wsum, lane, wid);
    if (T2 >= kk && (T2 - hv) < kk)
        { s_pref = (pref << 10) | (unsigned)t; s_k = kk - (T2 - hv); }
    __syncthreads();
    pref = s_pref;                            // 22-bit prefix
    kk = s_k;
    __syncthreads();

    // ---- pass 3: low 10 bits among (bits>>10)==pref
    hist[t] = 0;
    __syncthreads();
    #pragma unroll
    for (int j = 0; j < 8; j++)
        if ((bits[j] >> 10) == pref)
            atomicAdd(&hist[bits[j] & 0x3FFu], 1u);
    __syncthreads();
    hv = hist[t];
    unsigned T3 = suffix_incl_1024(hv, wsum, lane, wid);
    if (T3 >= kk && (T3 - hv) < kk)
        s_pref = (pref << 10) | (unsigned)t;
    __syncthreads();
    const unsigned thr = s_pref;              // exact k-th largest |h| bits

    #pragma unroll
    for (int j = 0; j < 8; j++) {
        int i = t + j * 1024;
        out[i] = (bits[j] >= thr) ? g_h[i] : 0.0f;
    }
}

// ---------------------------------------------------------------------------
template <typename F, typename... Args>
static inline void launch_pdl(F func, dim3 grid, dim3 block, Args... args) {
    cudaLaunchConfig_t cfg = {};
    cfg.gridDim = grid;
    cfg.blockDim = block;
    cfg.dynamicSmemBytes = 0;
    cudaLaunchAttribute attr[1];
    attr[0].id = cudaLaunchAttributeProgrammaticStreamSerialization;
    attr[0].val.programmaticStreamSerializationAllowed = 1;
    cfg.attrs = attr;
    cfg.numAttrs = 1;
    cudaLaunchKernelEx(&cfg, func, args...);
}

extern "C" void kernel_launch(void* const* d_in, const int* in_sizes, int n_in,
                              void* d_out, int out_size) {
    const float* x_in        = (const float*)d_in[0];
    const float* state_num   = (const float*)d_in[1];
    const float* state_den   = (const float*)d_in[2];
    const float* pred        = (const float*)d_in[3];
    const float* norm_w      = (const float*)d_in[4];
    const float* Wr          = (const float*)d_in[5];
    const float* Wk          = (const float*)d_in[6];
    const float* Wv          = (const float*)d_in[7];
    const float* Wo          = (const float*)d_in[8];
    const float* decay_param = (const float*)d_in[9];
    const float* W_time      = (const float*)d_in[10];
    const float* step_pos    = (const float*)d_in[11];
    const int*   dt          = (const int*)d_in[12];
    float* out = (float*)d_out;

    k_rms<<<1, 1024>>>(x_in, pred, norm_w);
    launch_pdl(k_mv3, dim3(3 * D), dim3(256), Wr, Wk, Wv);
    launch_pdl(k_gate, dim3(D / 256), dim3(256), state_num, state_den,
               decay_param, W_time, step_pos, dt);
    launch_pdl(k_mv_o, dim3(D), dim3(256), Wo);
    launch_pdl(k_kwta, dim3(1), dim3(1024), out);
}

// round 16
// speedup vs baseline: 1.0146x; 1.0146x over previous
#include <cuda_runtime.h>
#include <math.h>

#define D 8192
#define M_TIME 16
#define RMS_EPS 1e-6f
#define DEN_EPS 1e-9f
#define KTOP 1024  // D/8

// Scratch (no allocations allowed)
__device__ __align__(16) float g_x[D];
__device__ __align__(16) float g_r[D];
__device__ __align__(16) float g_k[D];
__device__ __align__(16) float g_v[D];
__device__ __align__(16) float g_y[D];
__device__ __align__(16) float g_h[D];

__device__ __forceinline__ float warp_sum(float v) {
    #pragma unroll
    for (int o = 16; o > 0; o >>= 1) v += __shfl_down_sync(0xffffffffu, v, o);
    return v;
}

// ---------------------------------------------------------------------------
// K1: x = rmsnorm(x_in + pred) * norm_w      (1 block, 1024 threads)
// ---------------------------------------------------------------------------
__global__ void k_rms(const float* __restrict__ x_in,
                      const float* __restrict__ pred,
                      const float* __restrict__ norm_w) {
    __shared__ float sh[32];
    __shared__ float s_inv;
    const int t = threadIdx.x;  // 1024
    float vals[8];
    float acc = 0.f;
    #pragma unroll
    for (int j = 0; j < 8; j++) {
        int i = t + j * 1024;
        float a = x_in[i] + pred[i];
        vals[j] = a;
        acc = fmaf(a, a, acc);
    }
    acc = warp_sum(acc);
    const int lane = t & 31, wid = t >> 5;
    if (lane == 0) sh[wid] = acc;
    __syncthreads();
    if (wid == 0) {
        float v = sh[lane];
        v = warp_sum(v);
        if (lane == 0) s_inv = rsqrtf(v * (1.0f / D) + RMS_EPS);
    }
    __syncthreads();
    const float inv = s_inv;
    #pragma unroll
    for (int j = 0; j < 8; j++) {
        int i = t + j * 1024;
        g_x[i] = vals[j] * inv * norm_w[i];
    }
}

// ---------------------------------------------------------------------------
// K2: r = sigmoid(Wr@x), k = Wk@x, v = Wv@x   (3*8192 blocks, 256 threads)
//     PDL: weight-slice loads are issued before the dependency sync (ptxas
//     is free to schedule them around it); only the g_x read needs the sync.
// ---------------------------------------------------------------------------
__global__ void __launch_bounds__(256) k_mv3(const float* __restrict__ Wr,
                                             const float* __restrict__ Wk,
                                             const float* __restrict__ Wv) {
    const int bid = blockIdx.x;
    const int mat = bid >> 13;           // 0..2
    const int row = bid & (D - 1);
    const float* W = (mat == 0 ? Wr : (mat == 1 ? Wk : Wv)) + (size_t)row * D;
    const float4* __restrict__ W4 = (const float4*)W;
    const float4* __restrict__ X4 = (const float4*)g_x;
    const int t = threadIdx.x;

    float4 w[8];
    #pragma unroll
    for (int j = 0; j < 8; j++) w[j] = W4[t + j * 256];

    cudaGridDependencySynchronize();

    float acc = 0.f;
    #pragma unroll
    for (int j = 0; j < 8; j++) {
        float4 x = X4[t + j * 256];
        acc = fmaf(w[j].x, x.x, acc);
        acc = fmaf(w[j].y, x.y, acc);
        acc = fmaf(w[j].z, x.z, acc);
        acc = fmaf(w[j].w, x.w, acc);
    }
    __shared__ float sh[8];
    acc = warp_sum(acc);
    const int lane = t & 31, wid = t >> 5;
    if (lane == 0) sh[wid] = acc;
    __syncthreads();
    if (t == 0) {
        float s = sh[0];
        #pragma unroll
        for (int i = 1; i < 8; i++) s += sh[i];
        if (mat == 0)      g_r[row] = 1.0f / (1.0f + __expf(-s));
        else if (mat == 1) g_k[row] = s;
        else               g_v[row] = s;
    }
}

// ---------------------------------------------------------------------------
// K3: decay/RoPE/gating -> y                 (32 blocks, 256 threads)
//     PDL: prefetch independent inputs before syncing on mv3's outputs.
// ---------------------------------------------------------------------------
__global__ void k_gate(const float* __restrict__ state_num,
                       const float* __restrict__ state_den,
                       const float* __restrict__ decay_param,
                       const float* __restrict__ W_time,
                       const float* __restrict__ step_pos,
                       const int*   __restrict__ dt) {
    const int i = blockIdx.x * blockDim.x + threadIdx.x;

    // Independent of mv3 outputs — issue before the dependency sync.
    float sn_in = state_num[i];
    float sd_in = state_den[i];
    float dp    = decay_param[i];
    int   n     = dt[0];
    float sp    = step_pos[0];

    float s = 1.0f / (1.0f + expf(-dp));
    float lam = s * s;
    float mul = 1.0f;
    for (int j = 0; j < n; j++) mul *= lam;

    cudaGridDependencySynchronize();

    float v = g_v[i];
    if (i < 2 * M_TIME) {
        int p = i >> 1;
        float th = sp * W_time[p];
        float c, sn_;
        sincosf(th, &sn_, &c);
        float v0 = g_v[2 * p];
        float v1 = g_v[2 * p + 1];
        v = (i & 1) ? (v0 * sn_ + v1 * c) : (v0 * c - v1 * sn_);
    }

    float w = expf(g_k[i]);
    float num = sn_in * mul * lam + w * v;
    float den = sd_in * mul * lam + w;
    g_y[i] = g_r[i] * (num / (den + DEN_EPS));
}

// ---------------------------------------------------------------------------
// K4: h = x + Wo@y                           (8192 blocks, 256 threads)
//     PDL: prefetch Wo slice before syncing on k_gate.
// ---------------------------------------------------------------------------
__global__ void __launch_bounds__(256) k_mv_o(const float* __restrict__ Wo) {
    const int row = blockIdx.x;
    const float4* __restrict__ W4 = (const float4*)(Wo + (size_t)row * D);
    const float4* __restrict__ Y4 = (const float4*)g_y;
    const int t = threadIdx.x;

    float4 w[8];
    #pragma unroll
    for (int j = 0; j < 8; j++) w[j] = W4[t + j * 256];

    cudaGridDependencySynchronize();

    float acc = 0.f;
    #pragma unroll
    for (int j = 0; j < 8; j++) {
        float4 y = Y4[t + j * 256];
        acc = fmaf(w[j].x, y.x, acc);
        acc = fmaf(w[j].y, y.y, acc);
        acc = fmaf(w[j].z, y.z, acc);
        acc = fmaf(w[j].w, y.w, acc);
    }
    __shared__ float sh[8];
    acc = warp_sum(acc);
    const int lane = t & 31, wid = t >> 5;
    if (lane == 0) sh[wid] = acc;
    __syncthreads();
    if (t == 0) {
        float s = sh[0];
        #pragma unroll
        for (int i = 1; i < 8; i++) s += sh[i];
        g_h[row] = g_x[row] + s;
    }
}

// ---------------------------------------------------------------------------
// K5: kWTA — exact k-th largest |h| via 4x8-bit radix select with parallel
//     suffix-scan bucket selection, then threshold. (1 block, 1024 threads)
// ---------------------------------------------------------------------------
__global__ void k_kwta(float* __restrict__ out) {
    cudaGridDependencySynchronize();
    __shared__ unsigned hist[256];
    __shared__ unsigned wsum[8];
    __shared__ unsigned s_prefix, s_k;
    const int t = threadIdx.x;  // 1024
    const int lane = t & 31, wid = t >> 5;

    unsigned bits[8];
    #pragma unroll
    for (int j = 0; j < 8; j++)
        bits[j] = __float_as_uint(fabsf(g_h[t + j * 1024]));

    unsigned prefix = 0;
    unsigned kk = KTOP;
    #pragma unroll
    for (int shift = 24; shift >= 0; shift -= 8) {
        if (t < 256) hist[t] = 0;
        __syncthreads();
        unsigned mask = (shift == 24) ? 0u : (~0u << (shift + 8));
        #pragma unroll
        for (int j = 0; j < 8; j++) {
            if ((bits[j] & mask) == prefix)
                atomicAdd(&hist[(bits[j] >> shift) & 255u], 1u);
        }
        __syncthreads();
        if (t < 256) {
            unsigned h = hist[t];
            unsigned v = h;
            #pragma unroll
            for (int o = 1; o < 32; o <<= 1) {
                unsigned u = __shfl_down_sync(0xffffffffu, v, o);
                if (lane + o < 32) v += u;
            }
            if (lane == 0) wsum[wid] = v;   // warp suffix totals
            __syncwarp();
        }
        __syncthreads();
        if (t < 256) {
            unsigned hi = 0;
            #pragma unroll
            for (int w = 0; w < 8; w++)
                if (w > wid) hi += wsum[w];
            unsigned h = hist[t];
            unsigned v = h;
            #pragma unroll
            for (int o = 1; o < 32; o <<= 1) {
                unsigned u = __shfl_down_sync(0xffffffffu, v, o);
                if (lane + o < 32) v += u;
            }
            unsigned S = v + hi;            // S[t]
            if (S >= kk && (S - h) < kk) {
                s_prefix = prefix | ((unsigned)t << shift);
                s_k = kk - (S - h);
            }
        }
        __syncthreads();
        prefix = s_prefix;
        kk = s_k;
        __syncthreads();
    }

    const float thr = __uint_as_float(prefix);
    #pragma unroll
    for (int j = 0; j < 8; j++) {
        int i = t + j * 1024;
        float h = g_h[i];
        out[i] = (fabsf(h) >= thr) ? h : 0.0f;
    }
}

// ---------------------------------------------------------------------------
template <typename F, typename... Args>
static inline void launch_pdl(F func, dim3 grid, dim3 block, Args... args) {
    cudaLaunchConfig_t cfg = {};
    cfg.gridDim = grid;
    cfg.blockDim = block;
    cfg.dynamicSmemBytes = 0;
    cudaLaunchAttribute attr[1];
    attr[0].id = cudaLaunchAttributeProgrammaticStreamSerialization;
    attr[0].val.programmaticStreamSerializationAllowed = 1;
    cfg.attrs = attr;
    cfg.numAttrs = 1;
    cudaLaunchKernelEx(&cfg, func, args...);
}

extern "C" void kernel_launch(void* const* d_in, const int* in_sizes, int n_in,
                              void* d_out, int out_size) {
    const float* x_in        = (const float*)d_in[0];
    const float* state_num   = (const float*)d_in[1];
    const float* state_den   = (const float*)d_in[2];
    const float* pred        = (const float*)d_in[3];
    const float* norm_w      = (const float*)d_in[4];
    const float* Wr          = (const float*)d_in[5];
    const float* Wk          = (const float*)d_in[6];
    const float* Wv          = (const float*)d_in[7];
    const float* Wo          = (const float*)d_in[8];
    const float* decay_param = (const float*)d_in[9];
    const float* W_time      = (const float*)d_in[10];
    const float* step_pos    = (const float*)d_in[11];
    const int*   dt          = (const int*)d_in[12];
    float* out = (float*)d_out;

    k_rms<<<1, 1024>>>(x_in, pred, norm_w);
    launch_pdl(k_mv3, dim3(3 * D), dim3(256), Wr, Wk, Wv);
    launch_pdl(k_gate, dim3(D / 256), dim3(256), state_num, state_den,
               decay_param, W_time, step_pos, dt);
    launch_pdl(k_mv_o, dim3(D), dim3(256), Wo);
    launch_pdl(k_kwta, dim3(1), dim3(1024), out);
}

// round 17
// speedup vs baseline: 1.0180x; 1.0034x over previous
#include <cuda_runtime.h>
#include <math.h>

#define D 8192
#define M_TIME 16
#define RMS_EPS 1e-6f
#define DEN_EPS 1e-9f
#define KTOP 1024  // D/8

// Scratch (no allocations allowed)
__device__ __align__(16) float g_x[D];
__device__ __align__(16) float g_r[D];
__device__ __align__(16) float g_k[D];
__device__ __align__(16) float g_v[D];
__device__ __align__(16) float g_y[D];
__device__ __align__(16) float g_h[D];

__device__ __forceinline__ float warp_sum(float v) {
    #pragma unroll
    for (int o = 16; o > 0; o >>= 1) v += __shfl_down_sync(0xffffffffu, v, o);
    return v;
}

// ---------------------------------------------------------------------------
// K1: x = rmsnorm(x_in + pred) * norm_w      (1 block, 1024 threads)
// ---------------------------------------------------------------------------
__global__ void k_rms(const float* __restrict__ x_in,
                      const float* __restrict__ pred,
                      const float* __restrict__ norm_w) {
    __shared__ float sh[32];
    __shared__ float s_inv;
    const int t = threadIdx.x;  // 1024
    float vals[8];
    float acc = 0.f;
    #pragma unroll
    for (int j = 0; j < 8; j++) {
        int i = t + j * 1024;
        float a = x_in[i] + pred[i];
        vals[j] = a;
        acc = fmaf(a, a, acc);
    }
    acc = warp_sum(acc);
    const int lane = t & 31, wid = t >> 5;
    if (lane == 0) sh[wid] = acc;
    __syncthreads();
    if (wid == 0) {
        float v = sh[lane];
        v = warp_sum(v);
        if (lane == 0) s_inv = rsqrtf(v * (1.0f / D) + RMS_EPS);
    }
    __syncthreads();
    const float inv = s_inv;
    #pragma unroll
    for (int j = 0; j < 8; j++) {
        int i = t + j * 1024;
        g_x[i] = vals[j] * inv * norm_w[i];
    }
}

// ---------------------------------------------------------------------------
// K2: r = sigmoid(Wr@x), k = Wk@x, v = Wv@x   (3*8192 blocks, 256 threads)
//     PDL prefetch-before-sync; weights loaded with streaming (evict-first)
//     cache policy — read exactly once.
// ---------------------------------------------------------------------------
__global__ void __launch_bounds__(256) k_mv3(const float* __restrict__ Wr,
                                             const float* __restrict__ Wk,
                                             const float* __restrict__ Wv) {
    const int bid = blockIdx.x;
    const int mat = bid >> 13;           // 0..2
    const int row = bid & (D - 1);
    const float* W = (mat == 0 ? Wr : (mat == 1 ? Wk : Wv)) + (size_t)row * D;
    const float4* __restrict__ W4 = (const float4*)W;
    const float4* __restrict__ X4 = (const float4*)g_x;
    const int t = threadIdx.x;

    float4 w[8];
    #pragma unroll
    for (int j = 0; j < 8; j++) w[j] = __ldcs(W4 + t + j * 256);

    cudaGridDependencySynchronize();

    float acc = 0.f;
    #pragma unroll
    for (int j = 0; j < 8; j++) {
        float4 x = X4[t + j * 256];
        acc = fmaf(w[j].x, x.x, acc);
        acc = fmaf(w[j].y, x.y, acc);
        acc = fmaf(w[j].z, x.z, acc);
        acc = fmaf(w[j].w, x.w, acc);
    }
    __shared__ float sh[8];
    acc = warp_sum(acc);
    const int lane = t & 31, wid = t >> 5;
    if (lane == 0) sh[wid] = acc;
    __syncthreads();
    if (t == 0) {
        float s = sh[0];
        #pragma unroll
        for (int i = 1; i < 8; i++) s += sh[i];
        if (mat == 0)      g_r[row] = 1.0f / (1.0f + __expf(-s));
        else if (mat == 1) g_k[row] = s;
        else               g_v[row] = s;
    }
}

// ---------------------------------------------------------------------------
// K3: decay/RoPE/gating -> y                 (32 blocks, 256 threads)
//     PDL: prefetch independent inputs before syncing on mv3's outputs.
// ---------------------------------------------------------------------------
__global__ void k_gate(const float* __restrict__ state_num,
                       const float* __restrict__ state_den,
                       const float* __restrict__ decay_param,
                       const float* __restrict__ W_time,
                       const float* __restrict__ step_pos,
                       const int*   __restrict__ dt) {
    const int i = blockIdx.x * blockDim.x + threadIdx.x;

    // Independent of mv3 outputs — issue before the dependency sync.
    float sn_in = state_num[i];
    float sd_in = state_den[i];
    float dp    = decay_param[i];
    int   n     = dt[0];
    float sp    = step_pos[0];

    float s = 1.0f / (1.0f + expf(-dp));
    float lam = s * s;
    float mul = 1.0f;
    for (int j = 0; j < n; j++) mul *= lam;

    cudaGridDependencySynchronize();

    float v = g_v[i];
    if (i < 2 * M_TIME) {
        int p = i >> 1;
        float th = sp * W_time[p];
        float c, sn_;
        sincosf(th, &sn_, &c);
        float v0 = g_v[2 * p];
        float v1 = g_v[2 * p + 1];
        v = (i & 1) ? (v0 * sn_ + v1 * c) : (v0 * c - v1 * sn_);
    }

    float w = expf(g_k[i]);
    float num = sn_in * mul * lam + w * v;
    float den = sd_in * mul * lam + w;
    g_y[i] = g_r[i] * (num / (den + DEN_EPS));
}

// ---------------------------------------------------------------------------
// K4: h = x + Wo@y                           (8192 blocks, 256 threads)
//     PDL prefetch-before-sync; streaming loads on Wo.
// ---------------------------------------------------------------------------
__global__ void __launch_bounds__(256) k_mv_o(const float* __restrict__ Wo) {
    const int row = blockIdx.x;
    const float4* __restrict__ W4 = (const float4*)(Wo + (size_t)row * D);
    const float4* __restrict__ Y4 = (const float4*)g_y;
    const int t = threadIdx.x;

    float4 w[8];
    #pragma unroll
    for (int j = 0; j < 8; j++) w[j] = __ldcs(W4 + t + j * 256);

    cudaGridDependencySynchronize();

    float acc = 0.f;
    #pragma unroll
    for (int j = 0; j < 8; j++) {
        float4 y = Y4[t + j * 256];
        acc = fmaf(w[j].x, y.x, acc);
        acc = fmaf(w[j].y, y.y, acc);
        acc = fmaf(w[j].z, y.z, acc);
        acc = fmaf(w[j].w, y.w, acc);
    }
    __shared__ float sh[8];
    acc = warp_sum(acc);
    const int lane = t & 31, wid = t >> 5;
    if (lane == 0) sh[wid] = acc;
    __syncthreads();
    if (t == 0) {
        float s = sh[0];
        #pragma unroll
        for (int i = 1; i < 8; i++) s += sh[i];
        g_h[row] = g_x[row] + s;
    }
}

// ---------------------------------------------------------------------------
// K5: kWTA — exact k-th largest |h| via 4x8-bit radix select with parallel
//     suffix-scan bucket selection, then threshold. (1 block, 1024 threads)
// ---------------------------------------------------------------------------
__global__ void k_kwta(float* __restrict__ out) {
    cudaGridDependencySynchronize();
    __shared__ unsigned hist[256];
    __shared__ unsigned wsum[8];
    __shared__ unsigned s_prefix, s_k;
    const int t = threadIdx.x;  // 1024
    const int lane = t & 31, wid = t >> 5;

    unsigned bits[8];
    #pragma unroll
    for (int j = 0; j < 8; j++)
        bits[j] = __float_as_uint(fabsf(g_h[t + j * 1024]));

    unsigned prefix = 0;
    unsigned kk = KTOP;
    #pragma unroll
    for (int shift = 24; shift >= 0; shift -= 8) {
        if (t < 256) hist[t] = 0;
        __syncthreads();
        unsigned mask = (shift == 24) ? 0u : (~0u << (shift + 8));
        #pragma unroll
        for (int j = 0; j < 8; j++) {
            if ((bits[j] & mask) == prefix)
                atomicAdd(&hist[(bits[j] >> shift) & 255u], 1u);
        }
        __syncthreads();
        if (t < 256) {
            unsigned h = hist[t];
            unsigned v = h;
            #pragma unroll
            for (int o = 1; o < 32; o <<= 1) {
                unsigned u = __shfl_down_sync(0xffffffffu, v, o);
                if (lane + o < 32) v += u;
            }
            if (lane == 0) wsum[wid] = v;   // warp suffix totals
            __syncwarp();
        }
        __syncthreads();
        if (t < 256) {
            unsigned hi = 0;
            #pragma unroll
            for (int w = 0; w < 8; w++)
                if (w > wid) hi += wsum[w];
            unsigned h = hist[t];
            unsigned v = h;
            #pragma unroll
            for (int o = 1; o < 32; o <<= 1) {
                unsigned u = __shfl_down_sync(0xffffffffu, v, o);
                if (lane + o < 32) v += u;
            }
            unsigned S = v + hi;            // S[t]
            if (S >= kk && (S - h) < kk) {
                s_prefix = prefix | ((unsigned)t << shift);
                s_k = kk - (S - h);
            }
        }
        __syncthreads();
        prefix = s_prefix;
        kk = s_k;
        __syncthreads();
    }

    const float thr = __uint_as_float(prefix);
    #pragma unroll
    for (int j = 0; j < 8; j++) {
        int i = t + j * 1024;
        float h = g_h[i];
        out[i] = (fabsf(h) >= thr) ? h : 0.0f;
    }
}

// ---------------------------------------------------------------------------
template <typename F, typename... Args>
static inline void launch_pdl(F func, dim3 grid, dim3 block, Args... args) {
    cudaLaunchConfig_t cfg = {};
    cfg.gridDim = grid;
    cfg.blockDim = block;
    cfg.dynamicSmemBytes = 0;
    cudaLaunchAttribute attr[1];
    attr[0].id = cudaLaunchAttributeProgrammaticStreamSerialization;
    attr[0].val.programmaticStreamSerializationAllowed = 1;
    cfg.attrs = attr;
    cfg.numAttrs = 1;
    cudaLaunchKernelEx(&cfg, func, args...);
}

extern "C" void kernel_launch(void* const* d_in, const int* in_sizes, int n_in,
                              void* d_out, int out_size) {
    const float* x_in        = (const float*)d_in[0];
    const float* state_num   = (const float*)d_in[1];
    const float* state_den   = (const float*)d_in[2];
    const float* pred        = (const float*)d_in[3];
    const float* norm_w      = (const float*)d_in[4];
    const float* Wr          = (const float*)d_in[5];
    const float* Wk          = (const float*)d_in[6];
    const float* Wv          = (const float*)d_in[7];
    const float* Wo          = (const float*)d_in[8];
    const float* decay_param = (const float*)d_in[9];
    const float* W_time      = (const float*)d_in[10];
    const float* step_pos    = (const float*)d_in[11];
    const int*   dt          = (const int*)d_in[12];
    float* out = (float*)d_out;

    k_rms<<<1, 1024>>>(x_in, pred, norm_w);
    launch_pdl(k_mv3, dim3(3 * D), dim3(256), Wr, Wk, Wv);
    launch_pdl(k_gate, dim3(D / 256), dim3(256), state_num, state_den,
               decay_param, W_time, step_pos, dt);
    launch_pdl(k_mv_o, dim3(D), dim3(256), Wo);
    launch_pdl(k_kwta, dim3(1), dim3(1024), out);
}